// round 5
// baseline (speedup 1.0000x reference)
#include <cuda_runtime.h>
#include <math.h>
#include <stdint.h>

#define B_   4
#define NM_  128
#define PS_  16
#define NP_  1024
#define D_   1024
#define H_   16
#define DH_  64
#define L_   12
#define FF_  4096
#define S_   1025

// ================= scratch =================
__device__ float g_patches[(size_t)B_ * NP_ * (NM_ * PS_)];
__device__ float g_pe     [(size_t)B_ * NP_ * D_];
__device__ float g_h      [(size_t)B_ * S_ * D_];
__device__ float g_y      [(size_t)B_ * S_ * D_];
__device__ float g_q      [(size_t)B_ * S_ * D_];
__device__ float g_k      [(size_t)B_ * S_ * D_];
__device__ float g_v      [(size_t)B_ * S_ * D_];
__device__ float g_o      [(size_t)B_ * S_ * D_];
__device__ float g_a1     [(size_t)B_ * S_ * FF_];
__device__ float g_a3     [(size_t)B_ * S_ * FF_];
__device__ float g_cos    [S_ * (DH_ / 2)];
__device__ float g_sin    [S_ * (DH_ / 2)];
__device__ float g_pwT [(size_t)D_ * (NM_ * PS_)];
__device__ float g_wqT [(size_t)L_ * D_ * D_];
__device__ float g_wkT [(size_t)L_ * D_ * D_];
__device__ float g_wvT [(size_t)L_ * D_ * D_];
__device__ float g_woT [(size_t)L_ * D_ * D_];
__device__ float g_w1T [(size_t)L_ * FF_ * D_];
__device__ float g_w3T [(size_t)L_ * FF_ * D_];
__device__ float g_w2T [(size_t)L_ * D_ * FF_];

// ================= tf32 helpers =================
__device__ __forceinline__ float f2tf32(float x) {
    uint32_t u; asm("cvt.rna.tf32.f32 %0, %1;" : "=r"(u) : "f"(x));
    return __uint_as_float(u);
}
__device__ __forceinline__ void mma8(float* c, const uint32_t* a, const uint32_t* b) {
    asm volatile(
        "mma.sync.aligned.m16n8k8.row.col.f32.tf32.tf32.f32 "
        "{%0,%1,%2,%3}, {%4,%5,%6,%7}, {%8,%9}, {%0,%1,%2,%3};"
        : "+f"(c[0]), "+f"(c[1]), "+f"(c[2]), "+f"(c[3])
        : "r"(a[0]), "r"(a[1]), "r"(a[2]), "r"(a[3]), "r"(b[0]), "r"(b[1]));
}

// fragment mapping (verified in R3):
// A value (rr 0..15, cc 0..7): lane=(rr&7)*4+(cc&3), reg=(rr>>3)+2*(cc>>2)
// B value (n 0..7, k 0..7):    lane=n*4+(k&3),       reg=k>>2
// C value: c0=(row=lane/4, col=2*(lane&3)), c1=col+1, c2/c3 = row+8

// ================= 128x128 GEMM (R3, proven) =================
__device__ __forceinline__ void g_load2(const float* __restrict__ P, int ldp,
                                        int maxR, int K, int rBase, int k0,
                                        int tid, float4* out)
{
    int r0 = tid >> 2;
    int gk = k0 + (tid & 3) * 4;
    #pragma unroll
    for (int i = 0; i < 2; i++) {
        int gr = rBase + r0 + i * 64;
        float4 v = {0.f, 0.f, 0.f, 0.f};
        if (gr < maxR) {
            const float* p = P + (long long)gr * ldp + gk;
            if (gk + 3 < K) v = *(const float4*)p;
            else {
                if (gk     < K) v.x = p[0];
                if (gk + 1 < K) v.y = p[1];
                if (gk + 2 < K) v.z = p[2];
            }
        }
        out[i] = v;
    }
}

__device__ __forceinline__ void sts_A2(float* __restrict__ As, const float4* pa, int tid)
{
    int r0  = tid >> 2;
    int ccb = (tid & 3) * 4;
    #pragma unroll
    for (int i = 0; i < 2; i++) {
        int r = r0 + i * 64;
        int mt = r >> 4, rr = r & 15;
        const float* v = (const float*)&pa[i];
        #pragma unroll
        for (int e = 0; e < 4; e++) {
            int c  = ccb + e;
            int kc = c >> 3, cc = c & 7;
            int ln  = (rr & 7) * 4 + (cc & 3);
            int reg = (rr >> 3) + 2 * (cc >> 2);
            As[((mt * 2 + kc) * 32 + ln) * 4 + reg] = f2tf32(v[e]);
        }
    }
}

__device__ __forceinline__ void sts_Bn(float* __restrict__ Bs, const float4* pb,
                                       int tid, int cnt)
{
    int n0  = tid >> 2;
    int ccb = (tid & 3) * 4;
    for (int i = 0; i < cnt; i++) {
        int n = n0 + i * 64;
        int nt = n >> 3, nr = n & 7;
        const float* v = (const float*)&pb[i];
        #pragma unroll
        for (int e = 0; e < 4; e++) {
            int c  = ccb + e;
            int kc = c >> 3, cc = c & 7;
            int ln  = nr * 4 + (cc & 3);
            int reg = cc >> 2;
            Bs[((nt * 2 + kc) * 32 + ln) * 2 + reg] = f2tf32(v[e]);
        }
    }
}

template<bool ACCUM, bool BIAS>
__global__ __launch_bounds__(256, 2) void mma_gemm_kernel(
    const float* __restrict__ A, const float* __restrict__ B,
    const float* __restrict__ bias, float* __restrict__ C,
    int M, int N, int K, int lda, int ldb, int ldc, float alpha)
{
    __shared__ __align__(16) float smA[2][2048];
    __shared__ __align__(16) float smB[2][2048];

    int tid = threadIdx.x, lane = tid & 31, wid = tid >> 5;
    int warp_m = wid >> 2, warp_n = wid & 3;

    int rowBase = blockIdx.y * 128;
    int colBase = blockIdx.x * 128;
    int T = (K + 15) >> 4;

    float acc[4][4][4] = {};
    float4 pa[2], pb[2];

    g_load2(A, lda, M, K, rowBase, 0, tid, pa);
    g_load2(B, ldb, N, K, colBase, 0, tid, pb);
    sts_A2(smA[0], pa, tid);
    sts_Bn(smB[0], pb, tid, 2);

    for (int t = 0; t < T; t++) {
        __syncthreads();
        if (t + 1 < T) {
            g_load2(A, lda, M, K, rowBase, (t + 1) << 4, tid, pa);
            g_load2(B, ldb, N, K, colBase, (t + 1) << 4, tid, pb);
        }
        const float* As = smA[t & 1];
        const float* Bs = smB[t & 1];
        #pragma unroll
        for (int kc = 0; kc < 2; kc++) {
            float4 af[4]; float2 bf[4];
            #pragma unroll
            for (int mt = 0; mt < 4; mt++)
                af[mt] = *(const float4*)&As[(((warp_m * 4 + mt) * 2 + kc) * 32 + lane) * 4];
            #pragma unroll
            for (int nt = 0; nt < 4; nt++)
                bf[nt] = *(const float2*)&Bs[(((warp_n * 4 + nt) * 2 + kc) * 32 + lane) * 2];
            #pragma unroll
            for (int mt = 0; mt < 4; mt++)
                #pragma unroll
                for (int nt = 0; nt < 4; nt++)
                    mma8(acc[mt][nt], (const uint32_t*)&af[mt], (const uint32_t*)&bf[nt]);
        }
        if (t + 1 < T) {
            __syncthreads();
            sts_A2(smA[(t + 1) & 1], pa, tid);
            sts_Bn(smB[(t + 1) & 1], pb, tid, 2);
        }
    }

    int rw = rowBase + warp_m * 64;
    int cw = colBase + warp_n * 32;
    #pragma unroll
    for (int mt = 0; mt < 4; mt++) {
        #pragma unroll
        for (int nt = 0; nt < 4; nt++) {
            int r0 = rw + mt * 16 + (lane >> 2);
            int gc = cw + nt * 8 + (lane & 3) * 2;
            const float* cf = acc[mt][nt];
            #pragma unroll
            for (int half = 0; half < 2; half++) {
                int gr = r0 + half * 8;
                if (gr >= M) continue;
                float v0 = cf[half * 2]     * alpha;
                float v1 = cf[half * 2 + 1] * alpha;
                float* crow = C + (long long)gr * ldc;
                if (gc + 1 < N) {
                    if (BIAS) {
                        float2 b2 = *(const float2*)(bias + gc);
                        v0 += b2.x; v1 += b2.y;
                    }
                    if (ACCUM) {
                        float2 c2 = *(const float2*)(crow + gc);
                        v0 += c2.x; v1 += c2.y;
                    }
                    float2 o2 = {v0, v1};
                    *(float2*)(crow + gc) = o2;
                } else if (gc < N) {
                    if (BIAS)  v0 += bias[gc];
                    if (ACCUM) v0 += crow[gc];
                    crow[gc] = v0;
                }
            }
        }
    }
}

// ================= 128x256 GEMM, 64x64 warp tiles (A/B experiment) =================
__device__ __forceinline__ void g_load4(const float* __restrict__ P, int ldp,
                                        int maxR, int K, int rBase, int k0,
                                        int tid, float4* out)
{
    int r0 = tid >> 2;
    int gk = k0 + (tid & 3) * 4;
    #pragma unroll
    for (int i = 0; i < 4; i++) {
        int gr = rBase + r0 + i * 64;
        float4 v = {0.f, 0.f, 0.f, 0.f};
        if (gr < maxR) {
            const float* p = P + (long long)gr * ldp + gk;
            if (gk + 3 < K) v = *(const float4*)p;
            else {
                if (gk     < K) v.x = p[0];
                if (gk + 1 < K) v.y = p[1];
                if (gk + 2 < K) v.z = p[2];
            }
        }
        out[i] = v;
    }
}

template<bool BIAS>
__global__ __launch_bounds__(256, 1) void mma_gemm256_kernel(
    const float* __restrict__ A, const float* __restrict__ B,
    const float* __restrict__ bias, float* __restrict__ C,
    int M, int N, int K, int lda, int ldb, int ldc, float alpha)
{
    __shared__ __align__(16) float smA[2][2048];
    __shared__ __align__(16) float smB[2][4096];

    int tid = threadIdx.x, lane = tid & 31, wid = tid >> 5;
    int warp_m = wid >> 2, warp_n = wid & 3;   // 2 x 4 over 128 x 256

    int rowBase = blockIdx.y * 128;
    int colBase = blockIdx.x * 256;
    int T = (K + 15) >> 4;

    float acc[4][8][4] = {};
    float4 pa[2], pb[4];

    g_load2(A, lda, M, K, rowBase, 0, tid, pa);
    g_load4(B, ldb, N, K, colBase, 0, tid, pb);
    sts_A2(smA[0], pa, tid);
    sts_Bn(smB[0], pb, tid, 4);

    for (int t = 0; t < T; t++) {
        __syncthreads();
        if (t + 1 < T) {
            g_load2(A, lda, M, K, rowBase, (t + 1) << 4, tid, pa);
            g_load4(B, ldb, N, K, colBase, (t + 1) << 4, tid, pb);
        }
        const float* As = smA[t & 1];
        const float* Bs = smB[t & 1];
        #pragma unroll
        for (int kc = 0; kc < 2; kc++) {
            float4 af[4]; float2 bf[8];
            #pragma unroll
            for (int mt = 0; mt < 4; mt++)
                af[mt] = *(const float4*)&As[(((warp_m * 4 + mt) * 2 + kc) * 32 + lane) * 4];
            #pragma unroll
            for (int nt = 0; nt < 8; nt++)
                bf[nt] = *(const float2*)&Bs[(((warp_n * 8 + nt) * 2 + kc) * 32 + lane) * 2];
            #pragma unroll
            for (int mt = 0; mt < 4; mt++)
                #pragma unroll
                for (int nt = 0; nt < 8; nt++)
                    mma8(acc[mt][nt], (const uint32_t*)&af[mt], (const uint32_t*)&bf[nt]);
        }
        if (t + 1 < T) {
            __syncthreads();
            sts_A2(smA[(t + 1) & 1], pa, tid);
            sts_Bn(smB[(t + 1) & 1], pb, tid, 4);
        }
    }

    int rw = rowBase + warp_m * 64;
    int cw = colBase + warp_n * 64;
    #pragma unroll
    for (int mt = 0; mt < 4; mt++) {
        #pragma unroll
        for (int nt = 0; nt < 8; nt++) {
            int r0 = rw + mt * 16 + (lane >> 2);
            int gc = cw + nt * 8 + (lane & 3) * 2;
            const float* cf = acc[mt][nt];
            #pragma unroll
            for (int half = 0; half < 2; half++) {
                int gr = r0 + half * 8;
                if (gr >= M) continue;
                float v0 = cf[half * 2]     * alpha;
                float v1 = cf[half * 2 + 1] * alpha;
                float* crow = C + (long long)gr * ldc;
                if (gc + 1 < N) {
                    if (BIAS) {
                        float2 b2 = *(const float2*)(bias + gc);
                        v0 += b2.x; v1 += b2.y;
                    }
                    float2 o2 = {v0, v1};
                    *(float2*)(crow + gc) = o2;
                } else if (gc < N) {
                    if (BIAS)  v0 += bias[gc];
                    crow[gc] = v0;
                }
            }
        }
    }
}

// ================= fused flash attention (tf32 mma, online softmax) =================
// grid (9, 16, 4): q-tile, head, batch. 256 threads = 8 warps, each warp owns 16 q rows.
// smem: Qs 32KB | Ks 32KB | Vs 32KB | Ps (per-warp A-frag staging) 64KB = 160KB dynamic.
#define ATTN_SMEM_BYTES (40960 * 4)

__global__ __launch_bounds__(256, 1) void attn_kernel(
    const float* __restrict__ q, const float* __restrict__ k,
    const float* __restrict__ v, float* __restrict__ o)
{
    extern __shared__ float sm[];
    float* Qs = sm;            // [mt 8][kc 8][32][4]
    float* Ks = sm + 8192;     // [nt 16][kc 8][32][2]
    float* Vs = sm + 16384;    // [ntv 8][kcv 16][32][2]
    float* Ps = sm + 24576;    // [warp 8][kcp 16][32][4]

    int tid = threadIdx.x, lane = tid & 31, wid = tid >> 5;
    int b = blockIdx.z, h = blockIdx.y, qb = blockIdx.x * 128;
    const long long base = (long long)b * S_ * D_ + h * DH_;

    // load Q tile (scale 1/8 folded in)
    #pragma unroll
    for (int i = 0; i < 8; i++) {
        int f4 = tid + i * 256;            // 2048 float4s
        int row = f4 >> 4, c4 = f4 & 15;
        int gq = qb + row;
        float4 val = {0.f, 0.f, 0.f, 0.f};
        if (gq < S_) val = *(const float4*)(q + base + (long long)gq * D_ + c4 * 4);
        const float* vv = (const float*)&val;
        int mt = row >> 4, rr = row & 15;
        #pragma unroll
        for (int e = 0; e < 4; e++) {
            int col = c4 * 4 + e;
            int kc = col >> 3, cc = col & 7;
            Qs[((mt * 8 + kc) * 32 + (rr & 7) * 4 + (cc & 3)) * 4 + (rr >> 3) + 2 * (cc >> 2)]
                = f2tf32(vv[e] * 0.125f);
        }
    }

    float mrow[2] = {-1e30f, -1e30f};
    float lrow[2] = {0.f, 0.f};
    float oacc[8][4] = {};
    float* Pw = Ps + wid * 2048;

    for (int kt = 0; kt < 9; kt++) {
        int kb = kt * 128;
        __syncthreads();
        // load K and V tiles
        #pragma unroll
        for (int i = 0; i < 8; i++) {
            int f4 = tid + i * 256;
            int key = f4 >> 4, c4 = f4 & 15;
            int gk = kb + key;
            float4 kv = {0.f, 0.f, 0.f, 0.f}, vv = {0.f, 0.f, 0.f, 0.f};
            if (gk < S_) {
                kv = *(const float4*)(k + base + (long long)gk * D_ + c4 * 4);
                vv = *(const float4*)(v + base + (long long)gk * D_ + c4 * 4);
            }
            const float* kp = (const float*)&kv;
            const float* vp = (const float*)&vv;
            #pragma unroll
            for (int e = 0; e < 4; e++) {
                int dh = c4 * 4 + e;
                Ks[(((key >> 3) * 8 + (dh >> 3)) * 32 + (key & 7) * 4 + (dh & 3)) * 2
                   + ((dh >> 2) & 1)] = f2tf32(kp[e]);
                Vs[(((dh >> 3) * 16 + (key >> 3)) * 32 + (dh & 7) * 4 + (key & 3)) * 2
                   + ((key >> 2) & 1)] = f2tf32(vp[e]);
            }
        }
        __syncthreads();

        // scores: warp's 16 rows x 128 keys
        float acc[16][4] = {};
        #pragma unroll
        for (int kc = 0; kc < 8; kc++) {
            float4 af = *(const float4*)&Qs[((wid * 8 + kc) * 32 + lane) * 4];
            #pragma unroll
            for (int nt = 0; nt < 16; nt++) {
                float2 bf = *(const float2*)&Ks[((nt * 8 + kc) * 32 + lane) * 2];
                mma8(acc[nt], (const uint32_t*)&af, (const uint32_t*)&bf);
            }
        }

        // online softmax
        int colb = (lane & 3) * 2;
        float tmax0 = -1e30f, tmax1 = -1e30f;
        #pragma unroll
        for (int nt = 0; nt < 16; nt++) {
            int c0 = kb + nt * 8 + colb;
            if (c0 < S_)     { tmax0 = fmaxf(tmax0, acc[nt][0]); tmax1 = fmaxf(tmax1, acc[nt][2]); }
            if (c0 + 1 < S_) { tmax0 = fmaxf(tmax0, acc[nt][1]); tmax1 = fmaxf(tmax1, acc[nt][3]); }
        }
        tmax0 = fmaxf(tmax0, __shfl_xor_sync(0xffffffffu, tmax0, 1));
        tmax0 = fmaxf(tmax0, __shfl_xor_sync(0xffffffffu, tmax0, 2));
        tmax1 = fmaxf(tmax1, __shfl_xor_sync(0xffffffffu, tmax1, 1));
        tmax1 = fmaxf(tmax1, __shfl_xor_sync(0xffffffffu, tmax1, 2));
        float mn0 = fmaxf(mrow[0], tmax0), mn1 = fmaxf(mrow[1], tmax1);
        float al0 = expf(mrow[0] - mn0),  al1 = expf(mrow[1] - mn1);
        float sum0 = 0.f, sum1 = 0.f;
        #pragma unroll
        for (int nt = 0; nt < 16; nt++) {
            int c0 = kb + nt * 8 + colb;
            float p0 = (c0     < S_) ? expf(acc[nt][0] - mn0) : 0.f;
            float p1 = (c0 + 1 < S_) ? expf(acc[nt][1] - mn0) : 0.f;
            float p2 = (c0     < S_) ? expf(acc[nt][2] - mn1) : 0.f;
            float p3 = (c0 + 1 < S_) ? expf(acc[nt][3] - mn1) : 0.f;
            acc[nt][0] = p0; acc[nt][1] = p1; acc[nt][2] = p2; acc[nt][3] = p3;
            sum0 += p0 + p1; sum1 += p2 + p3;
        }
        sum0 += __shfl_xor_sync(0xffffffffu, sum0, 1);
        sum0 += __shfl_xor_sync(0xffffffffu, sum0, 2);
        sum1 += __shfl_xor_sync(0xffffffffu, sum1, 1);
        sum1 += __shfl_xor_sync(0xffffffffu, sum1, 2);
        lrow[0] = lrow[0] * al0 + sum0;
        lrow[1] = lrow[1] * al1 + sum1;
        mrow[0] = mn0; mrow[1] = mn1;
        #pragma unroll
        for (int nt = 0; nt < 8; nt++) {
            oacc[nt][0] *= al0; oacc[nt][1] *= al0;
            oacc[nt][2] *= al1; oacc[nt][3] *= al1;
        }

        // stage P (tf32) into per-warp A-fragment layout
        int rrA = lane >> 2;
        #pragma unroll
        for (int nt = 0; nt < 16; nt++) {
            #pragma unroll
            for (int e = 0; e < 2; e++) {
                int col = nt * 8 + colb + e;
                int kcp = col >> 3, cc = col & 7;
                int ln = rrA * 4 + (cc & 3);
                int rh = 2 * (cc >> 2);
                Pw[(kcp * 32 + ln) * 4 + rh]     = f2tf32(acc[nt][e]);      // rows 0..7
                Pw[(kcp * 32 + ln) * 4 + rh + 1] = f2tf32(acc[nt][e + 2]);  // rows 8..15
            }
        }
        __syncwarp();

        // O += P @ V
        #pragma unroll
        for (int kcv = 0; kcv < 16; kcv++) {
            float4 paf = *(const float4*)&Pw[(kcv * 32 + lane) * 4];
            #pragma unroll
            for (int ntv = 0; ntv < 8; ntv++) {
                float2 bf = *(const float2*)&Vs[((ntv * 16 + kcv) * 32 + lane) * 2];
                mma8(oacc[ntv], (const uint32_t*)&paf, (const uint32_t*)&bf);
            }
        }
        __syncwarp();
    }

    // epilogue
    int row = wid * 16 + (lane >> 2);
    #pragma unroll
    for (int half = 0; half < 2; half++) {
        int gq = qb + row + half * 8;
        if (gq >= S_) continue;
        float invl = 1.f / lrow[half];
        float* orow = o + base + (long long)gq * D_;
        #pragma unroll
        for (int ntv = 0; ntv < 8; ntv++) {
            int col = ntv * 8 + (lane & 3) * 2;
            float2 val = { oacc[ntv][half * 2] * invl, oacc[ntv][half * 2 + 1] * invl };
            *(float2*)(orow + col) = val;
        }
    }
}

// ================= transposes =================
__global__ void transpose_kernel(const float* __restrict__ src, float* __restrict__ dst,
                                 int R, int C, long long sS, long long sD)
{
    __shared__ float t[32][33];
    const float* s = src + (long long)blockIdx.z * sS;
    float* d = dst + (long long)blockIdx.z * sD;
    int c0 = blockIdx.x * 32, r0 = blockIdx.y * 32;
    #pragma unroll
    for (int i = 0; i < 4; i++) {
        int r = r0 + threadIdx.y + i * 8, c = c0 + threadIdx.x;
        if (r < R && c < C) t[threadIdx.y + i * 8][threadIdx.x] = s[(long long)r * C + c];
    }
    __syncthreads();
    #pragma unroll
    for (int i = 0; i < 4; i++) {
        int r = c0 + threadIdx.y + i * 8, c = r0 + threadIdx.x;
        if (r < C && c < R) d[(long long)r * R + c] = t[threadIdx.x][threadIdx.y + i * 8];
    }
}

// ================= layernorm =================
__device__ __forceinline__ void ln_row_1024(const float* __restrict__ x,
                                            float* __restrict__ y,
                                            const float* __restrict__ gw,
                                            const float* __restrict__ bw)
{
    __shared__ float sh1[32], sh2[32];
    float v[4];
    float s = 0.f, ss = 0.f;
    #pragma unroll
    for (int i = 0; i < 4; i++) {
        v[i] = x[threadIdx.x + i * 256];
        s += v[i]; ss += v[i] * v[i];
    }
    #pragma unroll
    for (int o = 16; o > 0; o >>= 1) {
        s  += __shfl_down_sync(0xffffffffu, s,  o);
        ss += __shfl_down_sync(0xffffffffu, ss, o);
    }
    int lane = threadIdx.x & 31, w = threadIdx.x >> 5;
    if (lane == 0) { sh1[w] = s; sh2[w] = ss; }
    __syncthreads();
    if (w == 0) {
        s  = lane < 8 ? sh1[lane] : 0.f;
        ss = lane < 8 ? sh2[lane] : 0.f;
        #pragma unroll
        for (int o = 4; o > 0; o >>= 1) {
            s  += __shfl_down_sync(0xffffffffu, s,  o);
            ss += __shfl_down_sync(0xffffffffu, ss, o);
        }
        if (lane == 0) { sh1[0] = s; sh2[0] = ss; }
    }
    __syncthreads();
    float mu  = sh1[0] * (1.f / D_);
    float var = sh2[0] * (1.f / D_) - mu * mu;
    float inv = rsqrtf(var + 1e-5f);
    #pragma unroll
    for (int i = 0; i < 4; i++) {
        int c = threadIdx.x + i * 256;
        y[c] = (v[i] - mu) * inv * gw[c] + bw[c];
    }
}

__global__ void layernorm_kernel(const float* __restrict__ in, float* __restrict__ out,
                                 const float* __restrict__ gw, const float* __restrict__ bw)
{
    long long row = blockIdx.x;
    ln_row_1024(in + row * D_, out + row * D_, gw, bw);
}

__global__ void patch_ln_kernel(const float* __restrict__ pe, float* __restrict__ h,
                                const float* __restrict__ gw, const float* __restrict__ bw)
{
    int row = blockIdx.x;
    int b = row >> 10, p = row & 1023;
    ln_row_1024(pe + (long long)row * D_, h + ((long long)b * S_ + 1 + p) * D_, gw, bw);
}

// ================= misc elementwise =================
__global__ void patchify_kernel(const float* __restrict__ x, float* __restrict__ p)
{
    long long t = (long long)blockIdx.x * blockDim.x + threadIdx.x;
    const long long total = (long long)B_ * NP_ * NM_ * PS_;
    if (t >= total) return;
    int c   = (int)(t & 2047);
    long long bp = t >> 11;
    int pidx = (int)(bp & (NP_ - 1));
    int b    = (int)(bp >> 10);
    int m  = c >> 4;
    int tt = c & 15;
    p[t] = x[((long long)b * NM_ + m) * (PS_ * NP_) + (long long)pidx * PS_ + tt];
}

__global__ void cls_kernel(float* __restrict__ h, const float* __restrict__ cls)
{
    int t = blockIdx.x * blockDim.x + threadIdx.x;
    if (t >= B_ * D_) return;
    int b = t >> 10, i = t & 1023;
    h[(long long)b * S_ * D_ + i] = cls[i];
}

__global__ void rope_table_kernel(float* __restrict__ ct, float* __restrict__ st)
{
    int idx = blockIdx.x * blockDim.x + threadIdx.x;
    if (idx >= S_ * (DH_ / 2)) return;
    int i = idx & 31, s = idx >> 5;
    double invf = pow(10000.0, -(double)(2 * i) / (double)DH_);
    double ang  = (double)s * invf;
    ct[idx] = (float)cos(ang);
    st[idx] = (float)sin(ang);
}

__global__ void rope_kernel(float* __restrict__ q, float* __restrict__ k,
                            const float* __restrict__ ct, const float* __restrict__ st)
{
    long long t = (long long)blockIdx.x * blockDim.x + threadIdx.x;
    const long long total = (long long)B_ * S_ * H_ * (DH_ / 2);
    if (t >= total) return;
    int i = (int)(t & 31);
    long long r = t >> 5;
    int h = (int)(r & (H_ - 1));
    long long bs = r >> 4;
    int s = (int)(bs % S_);
    float c  = ct[s * 32 + i];
    float sn = st[s * 32 + i];
    long long base = bs * D_ + (long long)h * DH_;
    float q0 = q[base + i], q1 = q[base + i + 32];
    q[base + i]      = q0 * c - q1 * sn;
    q[base + i + 32] = q1 * c + q0 * sn;
    float k0 = k[base + i], k1 = k[base + i + 32];
    k[base + i]      = k0 * c - k1 * sn;
    k[base + i + 32] = k1 * c + k0 * sn;
}

__global__ void swiglu_kernel(float* __restrict__ a1, const float* __restrict__ a3)
{
    long long t = (long long)blockIdx.x * blockDim.x + threadIdx.x;
    const long long total = (long long)B_ * S_ * FF_;
    if (t >= total) return;
    float x = a1[t];
    float sig = 1.f / (1.f + expf(-x));
    a1[t] = x * sig * a3[t];
}

// ================= host side =================
static inline void run_gemm128(const float* A, const float* B, const float* bias, float* C,
                               int M, int N, int K, int lda, int ldb, int ldc,
                               float alpha, bool accum)
{
    dim3 grid((N + 127) / 128, (M + 127) / 128), block(256);
    if (accum)
        mma_gemm_kernel<true, true><<<grid, block>>>(A, B, bias, C, M, N, K, lda, ldb, ldc, alpha);
    else
        mma_gemm_kernel<false, true><<<grid, block>>>(A, B, bias, C, M, N, K, lda, ldb, ldc, alpha);
}

static inline void run_gemm256(const float* A, const float* B, const float* bias, float* C,
                               int M, int N, int K, int lda, int ldb, int ldc, float alpha)
{
    dim3 grid((N + 255) / 256, (M + 127) / 128), block(256);
    mma_gemm256_kernel<true><<<grid, block>>>(A, B, bias, C, M, N, K, lda, ldb, ldc, alpha);
}

extern "C" void kernel_launch(void* const* d_in, const int* in_sizes, int n_in,
                              void* d_out, int out_size)
{
    (void)in_sizes; (void)n_in; (void)out_size;
    const float* x        = (const float*)d_in[0];
    const float* patch_w  = (const float*)d_in[1];
    const float* patch_b  = (const float*)d_in[2];
    const float* pln_g    = (const float*)d_in[3];
    const float* pln_b    = (const float*)d_in[4];
    const float* cls_tok  = (const float*)d_in[5];
    const float* ln1_g    = (const float*)d_in[6];
    const float* ln1_b    = (const float*)d_in[7];
    const float* wq       = (const float*)d_in[8];
    const float* bq       = (const float*)d_in[9];
    const float* wk       = (const float*)d_in[10];
    const float* bk       = (const float*)d_in[11];
    const float* wv       = (const float*)d_in[12];
    const float* bv       = (const float*)d_in[13];
    const float* wo       = (const float*)d_in[14];
    const float* bo       = (const float*)d_in[15];
    const float* ln2_g    = (const float*)d_in[16];
    const float* ln2_b    = (const float*)d_in[17];
    const float* w1       = (const float*)d_in[18];
    const float* b1       = (const float*)d_in[19];
    const float* w2       = (const float*)d_in[20];
    const float* b2       = (const float*)d_in[21];
    const float* w3       = (const float*)d_in[22];
    const float* b3       = (const float*)d_in[23];
    const float* lnf_g    = (const float*)d_in[24];
    const float* lnf_b    = (const float*)d_in[25];
    float* out = (float*)d_out;

    float *patches, *pe, *h, *y, *q, *k, *v, *o, *a1, *a3, *ct, *st;
    float *pwT, *wqT, *wkT, *wvT, *woT, *w1T, *w3T, *w2T;
    cudaGetSymbolAddress((void**)&patches, g_patches);
    cudaGetSymbolAddress((void**)&pe, g_pe);
    cudaGetSymbolAddress((void**)&h,  g_h);
    cudaGetSymbolAddress((void**)&y,  g_y);
    cudaGetSymbolAddress((void**)&q,  g_q);
    cudaGetSymbolAddress((void**)&k,  g_k);
    cudaGetSymbolAddress((void**)&v,  g_v);
    cudaGetSymbolAddress((void**)&o,  g_o);
    cudaGetSymbolAddress((void**)&a1, g_a1);
    cudaGetSymbolAddress((void**)&a3, g_a3);
    cudaGetSymbolAddress((void**)&ct, g_cos);
    cudaGetSymbolAddress((void**)&st, g_sin);
    cudaGetSymbolAddress((void**)&pwT, g_pwT);
    cudaGetSymbolAddress((void**)&wqT, g_wqT);
    cudaGetSymbolAddress((void**)&wkT, g_wkT);
    cudaGetSymbolAddress((void**)&wvT, g_wvT);
    cudaGetSymbolAddress((void**)&woT, g_woT);
    cudaGetSymbolAddress((void**)&w1T, g_w1T);
    cudaGetSymbolAddress((void**)&w3T, g_w3T);
    cudaGetSymbolAddress((void**)&w2T, g_w2T);

    cudaFuncSetAttribute(attn_kernel, cudaFuncAttributeMaxDynamicSharedMemorySize,
                         ATTN_SMEM_BYTES);

    const int MR = B_ * S_;
    dim3 tb(32, 8);

    // weight transposes to [N,K] K-major
    transpose_kernel<<<dim3(32, 64, 1),  tb>>>(patch_w, pwT, NM_ * PS_, D_, 0, 0);
    transpose_kernel<<<dim3(32, 32, L_), tb>>>(wq, wqT, D_, D_, (long long)D_ * D_, (long long)D_ * D_);
    transpose_kernel<<<dim3(32, 32, L_), tb>>>(wk, wkT, D_, D_, (long long)D_ * D_, (long long)D_ * D_);
    transpose_kernel<<<dim3(32, 32, L_), tb>>>(wv, wvT, D_, D_, (long long)D_ * D_, (long long)D_ * D_);
    transpose_kernel<<<dim3(32, 32, L_), tb>>>(wo, woT, D_, D_, (long long)D_ * D_, (long long)D_ * D_);
    transpose_kernel<<<dim3(128, 32, L_), tb>>>(w1, w1T, D_, FF_, (long long)D_ * FF_, (long long)D_ * FF_);
    transpose_kernel<<<dim3(128, 32, L_), tb>>>(w3, w3T, D_, FF_, (long long)D_ * FF_, (long long)D_ * FF_);
    transpose_kernel<<<dim3(32, 128, L_), tb>>>(w2, w2T, FF_, D_, (long long)D_ * FF_, (long long)D_ * FF_);

    {
        long long n = (long long)B_ * NP_ * NM_ * PS_;
        patchify_kernel<<<(int)((n + 255) / 256), 256>>>(x, patches);
    }
    rope_table_kernel<<<(S_ * 32 + 255) / 256, 256>>>(ct, st);

    // patch embed (new 256-wide kernel)
    run_gemm256(patches, pwT, patch_b, pe, B_ * NP_, D_, NM_ * PS_,
                NM_ * PS_, NM_ * PS_, D_, 1.f);
    patch_ln_kernel<<<B_ * NP_, 256>>>(pe, h, pln_g, pln_b);
    cls_kernel<<<(B_ * D_ + 255) / 256, 256>>>(h, cls_tok);

    for (int l = 0; l < L_; l++) {
        const float* WqT = wqT + (size_t)l * D_ * D_;
        const float* WkT = wkT + (size_t)l * D_ * D_;
        const float* WvT = wvT + (size_t)l * D_ * D_;
        const float* WoT = woT + (size_t)l * D_ * D_;
        const float* W1T = w1T + (size_t)l * D_ * FF_;
        const float* W3T = w3T + (size_t)l * D_ * FF_;
        const float* W2T = w2T + (size_t)l * D_ * FF_;

        layernorm_kernel<<<MR, 256>>>(h, y, ln1_g + (size_t)l * D_, ln1_b + (size_t)l * D_);

        // QKV on old 128-wide kernel (A/B experiment control group)
        run_gemm128(y, WqT, bq + (size_t)l * D_, q, MR, D_, D_, D_, D_, D_, 1.f, false);
        run_gemm128(y, WkT, bk + (size_t)l * D_, k, MR, D_, D_, D_, D_, D_, 1.f, false);
        run_gemm128(y, WvT, bv + (size_t)l * D_, v, MR, D_, D_, D_, D_, D_, 1.f, false);

        {
            long long n = (long long)B_ * S_ * H_ * (DH_ / 2);
            rope_kernel<<<(int)((n + 255) / 256), 256>>>(q, k, ct, st);
        }

        // fused flash attention -> o
        attn_kernel<<<dim3(9, H_, B_), 256, ATTN_SMEM_BYTES>>>(q, k, v, o);

        // h += o @ Wo + bo
        run_gemm128(o, WoT, bo + (size_t)l * D_, h, MR, D_, D_, D_, D_, D_, 1.f, true);

        layernorm_kernel<<<MR, 256>>>(h, y, ln2_g + (size_t)l * D_, ln2_b + (size_t)l * D_);

        // MLP up-projections on new 256-wide kernel (treatment group)
        run_gemm256(y, W1T, b1 + (size_t)l * FF_, a1, MR, FF_, D_, D_, D_, FF_, 1.f);
        run_gemm256(y, W3T, b3 + (size_t)l * FF_, a3, MR, FF_, D_, D_, D_, FF_, 1.f);

        {
            long long n = (long long)B_ * S_ * FF_;
            swiglu_kernel<<<(int)((n + 255) / 256), 256>>>(a1, a3);
        }

        // h += swiglu @ W2 + b2 (old kernel, accumulating)
        run_gemm128(a1, W2T, b2 + (size_t)l * D_, h, MR, D_, FF_, FF_, FF_, D_, 1.f, true);
    }

    layernorm_kernel<<<MR, 256>>>(h, out, lnf_g, lnf_b);
}

// round 6
// speedup vs baseline: 1.4919x; 1.4919x over previous
#include <cuda_runtime.h>
#include <math.h>
#include <stdint.h>

#define B_   4
#define NM_  128
#define PS_  16
#define NP_  1024
#define D_   1024
#define H_   16
#define DH_  64
#define L_   12
#define FF_  4096
#define S_   1025

// ================= scratch =================
__device__ float g_patches[(size_t)B_ * NP_ * (NM_ * PS_)];
__device__ float g_pe     [(size_t)B_ * NP_ * D_];
__device__ float g_h      [(size_t)B_ * S_ * D_];
__device__ float g_y      [(size_t)B_ * S_ * D_];
__device__ float g_q      [(size_t)B_ * S_ * D_];
__device__ float g_k      [(size_t)B_ * S_ * D_];
__device__ float g_v      [(size_t)B_ * S_ * D_];
__device__ float g_o      [(size_t)B_ * S_ * D_];
__device__ float g_a1     [(size_t)B_ * S_ * FF_];
__device__ float g_a3     [(size_t)B_ * S_ * FF_];
__device__ float g_cos    [S_ * (DH_ / 2)];
__device__ float g_sin    [S_ * (DH_ / 2)];
__device__ float g_pwT [(size_t)D_ * (NM_ * PS_)];
__device__ float g_wqT [(size_t)L_ * D_ * D_];
__device__ float g_wkT [(size_t)L_ * D_ * D_];
__device__ float g_wvT [(size_t)L_ * D_ * D_];
__device__ float g_woT [(size_t)L_ * D_ * D_];
__device__ float g_w1T [(size_t)L_ * FF_ * D_];
__device__ float g_w3T [(size_t)L_ * FF_ * D_];
__device__ float g_w2T [(size_t)L_ * D_ * FF_];

// ================= tf32 helpers =================
__device__ __forceinline__ float f2tf32(float x) {
    uint32_t u; asm("cvt.rna.tf32.f32 %0, %1;" : "=r"(u) : "f"(x));
    return __uint_as_float(u);
}
__device__ __forceinline__ void mma8(float* c, const uint32_t* a, const uint32_t* b) {
    asm volatile(
        "mma.sync.aligned.m16n8k8.row.col.f32.tf32.tf32.f32 "
        "{%0,%1,%2,%3}, {%4,%5,%6,%7}, {%8,%9}, {%0,%1,%2,%3};"
        : "+f"(c[0]), "+f"(c[1]), "+f"(c[2]), "+f"(c[3])
        : "r"(a[0]), "r"(a[1]), "r"(a[2]), "r"(a[3]), "r"(b[0]), "r"(b[1]));
}

// fragment mapping (verified R3):
// A value (rr 0..15, cc 0..7): lane=(rr&7)*4+(cc&3), reg=(rr>>3)+2*(cc>>2)
// B value (n 0..7, k 0..7):    lane=n*4+(k&3),       reg=k>>2
// C value: c0=(row=lane/4, col=2*(lane&3)), c1=col+1, c2/c3 = row+8

// ================= 128x128 GEMM (R3, proven) =================
__device__ __forceinline__ void g_load2(const float* __restrict__ P, int ldp,
                                        int maxR, int K, int rBase, int k0,
                                        int tid, float4* out)
{
    int r0 = tid >> 2;
    int gk = k0 + (tid & 3) * 4;
    #pragma unroll
    for (int i = 0; i < 2; i++) {
        int gr = rBase + r0 + i * 64;
        float4 v = {0.f, 0.f, 0.f, 0.f};
        if (gr < maxR) {
            const float* p = P + (long long)gr * ldp + gk;
            if (gk + 3 < K) v = *(const float4*)p;
            else {
                if (gk     < K) v.x = p[0];
                if (gk + 1 < K) v.y = p[1];
                if (gk + 2 < K) v.z = p[2];
            }
        }
        out[i] = v;
    }
}

__device__ __forceinline__ void sts_A2(float* __restrict__ As, const float4* pa, int tid)
{
    int r0  = tid >> 2;
    int ccb = (tid & 3) * 4;
    #pragma unroll
    for (int i = 0; i < 2; i++) {
        int r = r0 + i * 64;
        int mt = r >> 4, rr = r & 15;
        const float* v = (const float*)&pa[i];
        #pragma unroll
        for (int e = 0; e < 4; e++) {
            int c  = ccb + e;
            int kc = c >> 3, cc = c & 7;
            int ln  = (rr & 7) * 4 + (cc & 3);
            int reg = (rr >> 3) + 2 * (cc >> 2);
            As[((mt * 2 + kc) * 32 + ln) * 4 + reg] = f2tf32(v[e]);
        }
    }
}

__device__ __forceinline__ void sts_B2(float* __restrict__ Bs, const float4* pb, int tid)
{
    int n0  = tid >> 2;
    int ccb = (tid & 3) * 4;
    #pragma unroll
    for (int i = 0; i < 2; i++) {
        int n = n0 + i * 64;
        int nt = n >> 3, nr = n & 7;
        const float* v = (const float*)&pb[i];
        #pragma unroll
        for (int e = 0; e < 4; e++) {
            int c  = ccb + e;
            int kc = c >> 3, cc = c & 7;
            int ln  = nr * 4 + (cc & 3);
            int reg = cc >> 2;
            Bs[((nt * 2 + kc) * 32 + ln) * 2 + reg] = f2tf32(v[e]);
        }
    }
}

template<bool ACCUM, bool BIAS>
__global__ __launch_bounds__(256, 2) void mma_gemm_kernel(
    const float* __restrict__ A, const float* __restrict__ B,
    const float* __restrict__ bias, float* __restrict__ C,
    int M, int N, int K, int lda, int ldb, int ldc, float alpha)
{
    __shared__ __align__(16) float smA[2][2048];
    __shared__ __align__(16) float smB[2][2048];

    int tid = threadIdx.x, lane = tid & 31, wid = tid >> 5;
    int warp_m = wid >> 2, warp_n = wid & 3;

    int rowBase = blockIdx.y * 128;
    int colBase = blockIdx.x * 128;
    int T = (K + 15) >> 4;

    float acc[4][4][4] = {};
    float4 pa[2], pb[2];

    g_load2(A, lda, M, K, rowBase, 0, tid, pa);
    g_load2(B, ldb, N, K, colBase, 0, tid, pb);
    sts_A2(smA[0], pa, tid);
    sts_B2(smB[0], pb, tid);

    for (int t = 0; t < T; t++) {
        __syncthreads();
        if (t + 1 < T) {
            g_load2(A, lda, M, K, rowBase, (t + 1) << 4, tid, pa);
            g_load2(B, ldb, N, K, colBase, (t + 1) << 4, tid, pb);
        }
        const float* As = smA[t & 1];
        const float* Bs = smB[t & 1];
        #pragma unroll
        for (int kc = 0; kc < 2; kc++) {
            float4 af[4]; float2 bf[4];
            #pragma unroll
            for (int mt = 0; mt < 4; mt++)
                af[mt] = *(const float4*)&As[(((warp_m * 4 + mt) * 2 + kc) * 32 + lane) * 4];
            #pragma unroll
            for (int nt = 0; nt < 4; nt++)
                bf[nt] = *(const float2*)&Bs[(((warp_n * 4 + nt) * 2 + kc) * 32 + lane) * 2];
            #pragma unroll
            for (int mt = 0; mt < 4; mt++)
                #pragma unroll
                for (int nt = 0; nt < 4; nt++)
                    mma8(acc[mt][nt], (const uint32_t*)&af[mt], (const uint32_t*)&bf[nt]);
        }
        if (t + 1 < T) {
            __syncthreads();
            sts_A2(smA[(t + 1) & 1], pa, tid);
            sts_B2(smB[(t + 1) & 1], pb, tid);
        }
    }

    int rw = rowBase + warp_m * 64;
    int cw = colBase + warp_n * 32;
    #pragma unroll
    for (int mt = 0; mt < 4; mt++) {
        #pragma unroll
        for (int nt = 0; nt < 4; nt++) {
            int r0 = rw + mt * 16 + (lane >> 2);
            int gc = cw + nt * 8 + (lane & 3) * 2;
            const float* cf = acc[mt][nt];
            #pragma unroll
            for (int half = 0; half < 2; half++) {
                int gr = r0 + half * 8;
                if (gr >= M) continue;
                float v0 = cf[half * 2]     * alpha;
                float v1 = cf[half * 2 + 1] * alpha;
                float* crow = C + (long long)gr * ldc;
                if (gc + 1 < N) {
                    if (BIAS) {
                        float2 b2 = *(const float2*)(bias + gc);
                        v0 += b2.x; v1 += b2.y;
                    }
                    if (ACCUM) {
                        float2 c2 = *(const float2*)(crow + gc);
                        v0 += c2.x; v1 += c2.y;
                    }
                    float2 o2 = {v0, v1};
                    *(float2*)(crow + gc) = o2;
                } else if (gc < N) {
                    if (BIAS)  v0 += bias[gc];
                    if (ACCUM) v0 += crow[gc];
                    crow[gc] = v0;
                }
            }
        }
    }
}

// ================= fused flash attention (tf32 mma, online softmax) =================
// grid (9, 16, 4): q-tile, head, batch. 256 threads = 8 warps, each warp owns 16 q rows.
// smem: Qs 32KB | Ks 32KB | Vs 32KB | Ps (per-warp A-frag staging) 64KB = 160KB dynamic.
#define ATTN_SMEM_BYTES (40960 * 4)

__global__ __launch_bounds__(256, 1) void attn_kernel(
    const float* __restrict__ q, const float* __restrict__ k,
    const float* __restrict__ v, float* __restrict__ o)
{
    extern __shared__ float sm[];
    float* Qs = sm;            // [mt 8][kc 8][32][4]
    float* Ks = sm + 8192;     // [nt 16][kc 8][32][2]
    float* Vs = sm + 16384;    // [ntv 8][kcv 16][32][2]
    float* Ps = sm + 24576;    // [warp 8][kcp 16][32][4]

    int tid = threadIdx.x, lane = tid & 31, wid = tid >> 5;
    int b = blockIdx.z, h = blockIdx.y, qb = blockIdx.x * 128;
    const long long base = (long long)b * S_ * D_ + h * DH_;

    // load Q tile (scale 1/8 folded in)
    #pragma unroll
    for (int i = 0; i < 8; i++) {
        int f4 = tid + i * 256;            // 2048 float4s
        int row = f4 >> 4, c4 = f4 & 15;
        int gq = qb + row;
        float4 val = {0.f, 0.f, 0.f, 0.f};
        if (gq < S_) val = *(const float4*)(q + base + (long long)gq * D_ + c4 * 4);
        const float* vv = (const float*)&val;
        int mt = row >> 4, rr = row & 15;
        #pragma unroll
        for (int e = 0; e < 4; e++) {
            int col = c4 * 4 + e;
            int kc = col >> 3, cc = col & 7;
            Qs[((mt * 8 + kc) * 32 + (rr & 7) * 4 + (cc & 3)) * 4 + (rr >> 3) + 2 * (cc >> 2)]
                = f2tf32(vv[e] * 0.125f);
        }
    }

    float mrow[2] = {-1e30f, -1e30f};
    float lrow[2] = {0.f, 0.f};
    float oacc[8][4] = {};
    float* Pw = Ps + wid * 2048;

    for (int kt = 0; kt < 9; kt++) {
        int kb = kt * 128;
        __syncthreads();
        // load K and V tiles
        #pragma unroll
        for (int i = 0; i < 8; i++) {
            int f4 = tid + i * 256;
            int key = f4 >> 4, c4 = f4 & 15;
            int gk = kb + key;
            float4 kv = {0.f, 0.f, 0.f, 0.f}, vv = {0.f, 0.f, 0.f, 0.f};
            if (gk < S_) {
                kv = *(const float4*)(k + base + (long long)gk * D_ + c4 * 4);
                vv = *(const float4*)(v + base + (long long)gk * D_ + c4 * 4);
            }
            const float* kp = (const float*)&kv;
            const float* vp = (const float*)&vv;
            #pragma unroll
            for (int e = 0; e < 4; e++) {
                int dh = c4 * 4 + e;
                Ks[(((key >> 3) * 8 + (dh >> 3)) * 32 + (key & 7) * 4 + (dh & 3)) * 2
                   + ((dh >> 2) & 1)] = f2tf32(kp[e]);
                Vs[(((dh >> 3) * 16 + (key >> 3)) * 32 + (dh & 7) * 4 + (key & 3)) * 2
                   + ((key >> 2) & 1)] = f2tf32(vp[e]);
            }
        }
        __syncthreads();

        // scores: warp's 16 rows x 128 keys
        float acc[16][4] = {};
        #pragma unroll
        for (int kc = 0; kc < 8; kc++) {
            float4 af = *(const float4*)&Qs[((wid * 8 + kc) * 32 + lane) * 4];
            #pragma unroll
            for (int nt = 0; nt < 16; nt++) {
                float2 bf = *(const float2*)&Ks[((nt * 8 + kc) * 32 + lane) * 2];
                mma8(acc[nt], (const uint32_t*)&af, (const uint32_t*)&bf);
            }
        }

        // online softmax
        int colb = (lane & 3) * 2;
        float tmax0 = -1e30f, tmax1 = -1e30f;
        #pragma unroll
        for (int nt = 0; nt < 16; nt++) {
            int c0 = kb + nt * 8 + colb;
            if (c0 < S_)     { tmax0 = fmaxf(tmax0, acc[nt][0]); tmax1 = fmaxf(tmax1, acc[nt][2]); }
            if (c0 + 1 < S_) { tmax0 = fmaxf(tmax0, acc[nt][1]); tmax1 = fmaxf(tmax1, acc[nt][3]); }
        }
        tmax0 = fmaxf(tmax0, __shfl_xor_sync(0xffffffffu, tmax0, 1));
        tmax0 = fmaxf(tmax0, __shfl_xor_sync(0xffffffffu, tmax0, 2));
        tmax1 = fmaxf(tmax1, __shfl_xor_sync(0xffffffffu, tmax1, 1));
        tmax1 = fmaxf(tmax1, __shfl_xor_sync(0xffffffffu, tmax1, 2));
        float mn0 = fmaxf(mrow[0], tmax0), mn1 = fmaxf(mrow[1], tmax1);
        float al0 = __expf(mrow[0] - mn0),  al1 = __expf(mrow[1] - mn1);
        float sum0 = 0.f, sum1 = 0.f;
        #pragma unroll
        for (int nt = 0; nt < 16; nt++) {
            int c0 = kb + nt * 8 + colb;
            float p0 = (c0     < S_) ? __expf(acc[nt][0] - mn0) : 0.f;
            float p1 = (c0 + 1 < S_) ? __expf(acc[nt][1] - mn0) : 0.f;
            float p2 = (c0     < S_) ? __expf(acc[nt][2] - mn1) : 0.f;
            float p3 = (c0 + 1 < S_) ? __expf(acc[nt][3] - mn1) : 0.f;
            acc[nt][0] = p0; acc[nt][1] = p1; acc[nt][2] = p2; acc[nt][3] = p3;
            sum0 += p0 + p1; sum1 += p2 + p3;
        }
        sum0 += __shfl_xor_sync(0xffffffffu, sum0, 1);
        sum0 += __shfl_xor_sync(0xffffffffu, sum0, 2);
        sum1 += __shfl_xor_sync(0xffffffffu, sum1, 1);
        sum1 += __shfl_xor_sync(0xffffffffu, sum1, 2);
        lrow[0] = lrow[0] * al0 + sum0;
        lrow[1] = lrow[1] * al1 + sum1;
        mrow[0] = mn0; mrow[1] = mn1;
        #pragma unroll
        for (int nt = 0; nt < 8; nt++) {
            oacc[nt][0] *= al0; oacc[nt][1] *= al0;
            oacc[nt][2] *= al1; oacc[nt][3] *= al1;
        }

        // stage P (tf32) into per-warp A-fragment layout
        int rrA = lane >> 2;
        #pragma unroll
        for (int nt = 0; nt < 16; nt++) {
            #pragma unroll
            for (int e = 0; e < 2; e++) {
                int col = nt * 8 + colb + e;
                int kcp = col >> 3, cc = col & 7;
                int ln = rrA * 4 + (cc & 3);
                int rh = 2 * (cc >> 2);
                Pw[(kcp * 32 + ln) * 4 + rh]     = f2tf32(acc[nt][e]);      // rows 0..7
                Pw[(kcp * 32 + ln) * 4 + rh + 1] = f2tf32(acc[nt][e + 2]);  // rows 8..15
            }
        }
        __syncwarp();

        // O += P @ V
        #pragma unroll
        for (int kcv = 0; kcv < 16; kcv++) {
            float4 paf = *(const float4*)&Pw[(kcv * 32 + lane) * 4];
            #pragma unroll
            for (int ntv = 0; ntv < 8; ntv++) {
                float2 bf = *(const float2*)&Vs[((ntv * 16 + kcv) * 32 + lane) * 2];
                mma8(oacc[ntv], (const uint32_t*)&paf, (const uint32_t*)&bf);
            }
        }
        __syncwarp();
    }

    // epilogue
    int row = wid * 16 + (lane >> 2);
    #pragma unroll
    for (int half = 0; half < 2; half++) {
        int gq = qb + row + half * 8;
        if (gq >= S_) continue;
        float invl = 1.f / lrow[half];
        float* orow = o + base + (long long)gq * D_;
        #pragma unroll
        for (int ntv = 0; ntv < 8; ntv++) {
            int col = ntv * 8 + (lane & 3) * 2;
            float2 val = { oacc[ntv][half * 2] * invl, oacc[ntv][half * 2 + 1] * invl };
            *(float2*)(orow + col) = val;
        }
    }
}

// ================= transposes =================
__global__ void transpose_kernel(const float* __restrict__ src, float* __restrict__ dst,
                                 int R, int C, long long sS, long long sD)
{
    __shared__ float t[32][33];
    const float* s = src + (long long)blockIdx.z * sS;
    float* d = dst + (long long)blockIdx.z * sD;
    int c0 = blockIdx.x * 32, r0 = blockIdx.y * 32;
    #pragma unroll
    for (int i = 0; i < 4; i++) {
        int r = r0 + threadIdx.y + i * 8, c = c0 + threadIdx.x;
        if (r < R && c < C) t[threadIdx.y + i * 8][threadIdx.x] = s[(long long)r * C + c];
    }
    __syncthreads();
    #pragma unroll
    for (int i = 0; i < 4; i++) {
        int r = c0 + threadIdx.y + i * 8, c = r0 + threadIdx.x;
        if (r < C && c < R) d[(long long)r * R + c] = t[threadIdx.x][threadIdx.y + i * 8];
    }
}

// ================= layernorm =================
__device__ __forceinline__ void ln_row_1024(const float* __restrict__ x,
                                            float* __restrict__ y,
                                            const float* __restrict__ gw,
                                            const float* __restrict__ bw)
{
    __shared__ float sh1[32], sh2[32];
    float v[4];
    float s = 0.f, ss = 0.f;
    #pragma unroll
    for (int i = 0; i < 4; i++) {
        v[i] = x[threadIdx.x + i * 256];
        s += v[i]; ss += v[i] * v[i];
    }
    #pragma unroll
    for (int o = 16; o > 0; o >>= 1) {
        s  += __shfl_down_sync(0xffffffffu, s,  o);
        ss += __shfl_down_sync(0xffffffffu, ss, o);
    }
    int lane = threadIdx.x & 31, w = threadIdx.x >> 5;
    if (lane == 0) { sh1[w] = s; sh2[w] = ss; }
    __syncthreads();
    if (w == 0) {
        s  = lane < 8 ? sh1[lane] : 0.f;
        ss = lane < 8 ? sh2[lane] : 0.f;
        #pragma unroll
        for (int o = 4; o > 0; o >>= 1) {
            s  += __shfl_down_sync(0xffffffffu, s,  o);
            ss += __shfl_down_sync(0xffffffffu, ss, o);
        }
        if (lane == 0) { sh1[0] = s; sh2[0] = ss; }
    }
    __syncthreads();
    float mu  = sh1[0] * (1.f / D_);
    float var = sh2[0] * (1.f / D_) - mu * mu;
    float inv = rsqrtf(var + 1e-5f);
    #pragma unroll
    for (int i = 0; i < 4; i++) {
        int c = threadIdx.x + i * 256;
        y[c] = (v[i] - mu) * inv * gw[c] + bw[c];
    }
}

__global__ void layernorm_kernel(const float* __restrict__ in, float* __restrict__ out,
                                 const float* __restrict__ gw, const float* __restrict__ bw)
{
    long long row = blockIdx.x;
    ln_row_1024(in + row * D_, out + row * D_, gw, bw);
}

__global__ void patch_ln_kernel(const float* __restrict__ pe, float* __restrict__ h,
                                const float* __restrict__ gw, const float* __restrict__ bw)
{
    int row = blockIdx.x;
    int b = row >> 10, p = row & 1023;
    ln_row_1024(pe + (long long)row * D_, h + ((long long)b * S_ + 1 + p) * D_, gw, bw);
}

// ================= misc elementwise =================
__global__ void patchify_kernel(const float* __restrict__ x, float* __restrict__ p)
{
    long long t = (long long)blockIdx.x * blockDim.x + threadIdx.x;
    const long long total = (long long)B_ * NP_ * NM_ * PS_;
    if (t >= total) return;
    int c   = (int)(t & 2047);
    long long bp = t >> 11;
    int pidx = (int)(bp & (NP_ - 1));
    int b    = (int)(bp >> 10);
    int m  = c >> 4;
    int tt = c & 15;
    p[t] = x[((long long)b * NM_ + m) * (PS_ * NP_) + (long long)pidx * PS_ + tt];
}

__global__ void cls_kernel(float* __restrict__ h, const float* __restrict__ cls)
{
    int t = blockIdx.x * blockDim.x + threadIdx.x;
    if (t >= B_ * D_) return;
    int b = t >> 10, i = t & 1023;
    h[(long long)b * S_ * D_ + i] = cls[i];
}

__global__ void rope_table_kernel(float* __restrict__ ct, float* __restrict__ st)
{
    int idx = blockIdx.x * blockDim.x + threadIdx.x;
    if (idx >= S_ * (DH_ / 2)) return;
    int i = idx & 31, s = idx >> 5;
    double invf = pow(10000.0, -(double)(2 * i) / (double)DH_);
    double ang  = (double)s * invf;
    ct[idx] = (float)cos(ang);
    st[idx] = (float)sin(ang);
}

__global__ void rope_kernel(float* __restrict__ q, float* __restrict__ k,
                            const float* __restrict__ ct, const float* __restrict__ st)
{
    long long t = (long long)blockIdx.x * blockDim.x + threadIdx.x;
    const long long total = (long long)B_ * S_ * H_ * (DH_ / 2);
    if (t >= total) return;
    int i = (int)(t & 31);
    long long r = t >> 5;
    int h = (int)(r & (H_ - 1));
    long long bs = r >> 4;
    int s = (int)(bs % S_);
    float c  = ct[s * 32 + i];
    float sn = st[s * 32 + i];
    long long base = bs * D_ + (long long)h * DH_;
    float q0 = q[base + i], q1 = q[base + i + 32];
    q[base + i]      = q0 * c - q1 * sn;
    q[base + i + 32] = q1 * c + q0 * sn;
    float k0 = k[base + i], k1 = k[base + i + 32];
    k[base + i]      = k0 * c - k1 * sn;
    k[base + i + 32] = k1 * c + k0 * sn;
}

__global__ void swiglu_kernel(float* __restrict__ a1, const float* __restrict__ a3)
{
    long long t = (long long)blockIdx.x * blockDim.x + threadIdx.x;
    const long long total = (long long)B_ * S_ * FF_;
    if (t >= total) return;
    float x = a1[t];
    float sig = 1.f / (1.f + expf(-x));
    a1[t] = x * sig * a3[t];
}

// ================= host side =================
static inline void run_gemm128(const float* A, const float* B, const float* bias, float* C,
                               int M, int N, int K, int lda, int ldb, int ldc,
                               float alpha, bool accum)
{
    dim3 grid((N + 127) / 128, (M + 127) / 128), block(256);
    if (accum)
        mma_gemm_kernel<true, true><<<grid, block>>>(A, B, bias, C, M, N, K, lda, ldb, ldc, alpha);
    else
        mma_gemm_kernel<false, true><<<grid, block>>>(A, B, bias, C, M, N, K, lda, ldb, ldc, alpha);
}

extern "C" void kernel_launch(void* const* d_in, const int* in_sizes, int n_in,
                              void* d_out, int out_size)
{
    (void)in_sizes; (void)n_in; (void)out_size;
    const float* x        = (const float*)d_in[0];
    const float* patch_w  = (const float*)d_in[1];
    const float* patch_b  = (const float*)d_in[2];
    const float* pln_g    = (const float*)d_in[3];
    const float* pln_b    = (const float*)d_in[4];
    const float* cls_tok  = (const float*)d_in[5];
    const float* ln1_g    = (const float*)d_in[6];
    const float* ln1_b    = (const float*)d_in[7];
    const float* wq       = (const float*)d_in[8];
    const float* bq       = (const float*)d_in[9];
    const float* wk       = (const float*)d_in[10];
    const float* bk       = (const float*)d_in[11];
    const float* wv       = (const float*)d_in[12];
    const float* bv       = (const float*)d_in[13];
    const float* wo       = (const float*)d_in[14];
    const float* bo       = (const float*)d_in[15];
    const float* ln2_g    = (const float*)d_in[16];
    const float* ln2_b    = (const float*)d_in[17];
    const float* w1       = (const float*)d_in[18];
    const float* b1       = (const float*)d_in[19];
    const float* w2       = (const float*)d_in[20];
    const float* b2       = (const float*)d_in[21];
    const float* w3       = (const float*)d_in[22];
    const float* b3       = (const float*)d_in[23];
    const float* lnf_g    = (const float*)d_in[24];
    const float* lnf_b    = (const float*)d_in[25];
    float* out = (float*)d_out;

    float *patches, *pe, *h, *y, *q, *k, *v, *o, *a1, *a3, *ct, *st;
    float *pwT, *wqT, *wkT, *wvT, *woT, *w1T, *w3T, *w2T;
    cudaGetSymbolAddress((void**)&patches, g_patches);
    cudaGetSymbolAddress((void**)&pe, g_pe);
    cudaGetSymbolAddress((void**)&h,  g_h);
    cudaGetSymbolAddress((void**)&y,  g_y);
    cudaGetSymbolAddress((void**)&q,  g_q);
    cudaGetSymbolAddress((void**)&k,  g_k);
    cudaGetSymbolAddress((void**)&v,  g_v);
    cudaGetSymbolAddress((void**)&o,  g_o);
    cudaGetSymbolAddress((void**)&a1, g_a1);
    cudaGetSymbolAddress((void**)&a3, g_a3);
    cudaGetSymbolAddress((void**)&ct, g_cos);
    cudaGetSymbolAddress((void**)&st, g_sin);
    cudaGetSymbolAddress((void**)&pwT, g_pwT);
    cudaGetSymbolAddress((void**)&wqT, g_wqT);
    cudaGetSymbolAddress((void**)&wkT, g_wkT);
    cudaGetSymbolAddress((void**)&wvT, g_wvT);
    cudaGetSymbolAddress((void**)&woT, g_woT);
    cudaGetSymbolAddress((void**)&w1T, g_w1T);
    cudaGetSymbolAddress((void**)&w3T, g_w3T);
    cudaGetSymbolAddress((void**)&w2T, g_w2T);

    cudaFuncSetAttribute(attn_kernel, cudaFuncAttributeMaxDynamicSharedMemorySize,
                         ATTN_SMEM_BYTES);

    const int MR = B_ * S_;
    dim3 tb(32, 8);

    // weight transposes to [N,K] K-major
    transpose_kernel<<<dim3(32, 64, 1),  tb>>>(patch_w, pwT, NM_ * PS_, D_, 0, 0);
    transpose_kernel<<<dim3(32, 32, L_), tb>>>(wq, wqT, D_, D_, (long long)D_ * D_, (long long)D_ * D_);
    transpose_kernel<<<dim3(32, 32, L_), tb>>>(wk, wkT, D_, D_, (long long)D_ * D_, (long long)D_ * D_);
    transpose_kernel<<<dim3(32, 32, L_), tb>>>(wv, wvT, D_, D_, (long long)D_ * D_, (long long)D_ * D_);
    transpose_kernel<<<dim3(32, 32, L_), tb>>>(wo, woT, D_, D_, (long long)D_ * D_, (long long)D_ * D_);
    transpose_kernel<<<dim3(128, 32, L_), tb>>>(w1, w1T, D_, FF_, (long long)D_ * FF_, (long long)D_ * FF_);
    transpose_kernel<<<dim3(128, 32, L_), tb>>>(w3, w3T, D_, FF_, (long long)D_ * FF_, (long long)D_ * FF_);
    transpose_kernel<<<dim3(32, 128, L_), tb>>>(w2, w2T, FF_, D_, (long long)D_ * FF_, (long long)D_ * FF_);

    {
        long long n = (long long)B_ * NP_ * NM_ * PS_;
        patchify_kernel<<<(int)((n + 255) / 256), 256>>>(x, patches);
    }
    rope_table_kernel<<<(S_ * 32 + 255) / 256, 256>>>(ct, st);

    // patch embed (back on proven 128-wide kernel)
    run_gemm128(patches, pwT, patch_b, pe, B_ * NP_, D_, NM_ * PS_,
                NM_ * PS_, NM_ * PS_, D_, 1.f, false);
    patch_ln_kernel<<<B_ * NP_, 256>>>(pe, h, pln_g, pln_b);
    cls_kernel<<<(B_ * D_ + 255) / 256, 256>>>(h, cls_tok);

    for (int l = 0; l < L_; l++) {
        const float* WqT = wqT + (size_t)l * D_ * D_;
        const float* WkT = wkT + (size_t)l * D_ * D_;
        const float* WvT = wvT + (size_t)l * D_ * D_;
        const float* WoT = woT + (size_t)l * D_ * D_;
        const float* W1T = w1T + (size_t)l * D_ * FF_;
        const float* W3T = w3T + (size_t)l * D_ * FF_;
        const float* W2T = w2T + (size_t)l * D_ * FF_;

        layernorm_kernel<<<MR, 256>>>(h, y, ln1_g + (size_t)l * D_, ln1_b + (size_t)l * D_);

        run_gemm128(y, WqT, bq + (size_t)l * D_, q, MR, D_, D_, D_, D_, D_, 1.f, false);
        run_gemm128(y, WkT, bk + (size_t)l * D_, k, MR, D_, D_, D_, D_, D_, 1.f, false);
        run_gemm128(y, WvT, bv + (size_t)l * D_, v, MR, D_, D_, D_, D_, D_, 1.f, false);

        {
            long long n = (long long)B_ * S_ * H_ * (DH_ / 2);
            rope_kernel<<<(int)((n + 255) / 256), 256>>>(q, k, ct, st);
        }

        // fused flash attention -> o
        attn_kernel<<<dim3(9, H_, B_), 256, ATTN_SMEM_BYTES>>>(q, k, v, o);

        // h += o @ Wo + bo
        run_gemm128(o, WoT, bo + (size_t)l * D_, h, MR, D_, D_, D_, D_, D_, 1.f, true);

        layernorm_kernel<<<MR, 256>>>(h, y, ln2_g + (size_t)l * D_, ln2_b + (size_t)l * D_);

        run_gemm128(y, W1T, b1 + (size_t)l * FF_, a1, MR, FF_, D_, D_, D_, FF_, 1.f, false);
        run_gemm128(y, W3T, b3 + (size_t)l * FF_, a3, MR, FF_, D_, D_, D_, FF_, 1.f, false);

        {
            long long n = (long long)B_ * S_ * FF_;
            swiglu_kernel<<<(int)((n + 255) / 256), 256>>>(a1, a3);
        }

        run_gemm128(a1, W2T, b2 + (size_t)l * D_, h, MR, D_, FF_, FF_, FF_, D_, 1.f, true);
    }

    layernorm_kernel<<<MR, 256>>>(h, out, lnf_g, lnf_b);
}

// round 7
// speedup vs baseline: 1.7370x; 1.1642x over previous
#include <cuda_runtime.h>
#include <math.h>
#include <stdint.h>

#define B_   4
#define NM_  128
#define PS_  16
#define NP_  1024
#define D_   1024
#define H_   16
#define DH_  64
#define L_   12
#define FF_  4096
#define S_   1025
#define RS_  20          // smem row stride (floats): 16 data + 4 pad -> conflict-free gather

// ================= scratch =================
__device__ float g_patches[(size_t)B_ * NP_ * (NM_ * PS_)];
__device__ float g_pe     [(size_t)B_ * NP_ * D_];
__device__ float g_h      [(size_t)B_ * S_ * D_];
__device__ float g_y      [(size_t)B_ * S_ * D_];
__device__ float g_q      [(size_t)B_ * S_ * D_];
__device__ float g_k      [(size_t)B_ * S_ * D_];
__device__ float g_v      [(size_t)B_ * S_ * D_];
__device__ float g_o      [(size_t)B_ * S_ * D_];
__device__ float g_a1     [(size_t)B_ * S_ * FF_];
__device__ float g_a3     [(size_t)B_ * S_ * FF_];
__device__ float g_cos    [S_ * (DH_ / 2)];
__device__ float g_sin    [S_ * (DH_ / 2)];
__device__ float g_pwT [(size_t)D_ * (NM_ * PS_)];
__device__ float g_wqT [(size_t)L_ * D_ * D_];
__device__ float g_wkT [(size_t)L_ * D_ * D_];
__device__ float g_wvT [(size_t)L_ * D_ * D_];
__device__ float g_woT [(size_t)L_ * D_ * D_];
__device__ float g_w1T [(size_t)L_ * FF_ * D_];
__device__ float g_w3T [(size_t)L_ * FF_ * D_];
__device__ float g_w2T [(size_t)L_ * D_ * FF_];

// ================= tf32 helpers =================
__device__ __forceinline__ float f2tf32(float x) {
    uint32_t u; asm("cvt.rna.tf32.f32 %0, %1;" : "=r"(u) : "f"(x));
    return __uint_as_float(u);
}
__device__ __forceinline__ void mma8(float* c, const uint32_t* a, const uint32_t* b) {
    asm volatile(
        "mma.sync.aligned.m16n8k8.row.col.f32.tf32.tf32.f32 "
        "{%0,%1,%2,%3}, {%4,%5,%6,%7}, {%8,%9}, {%0,%1,%2,%3};"
        : "+f"(c[0]), "+f"(c[1]), "+f"(c[2]), "+f"(c[3])
        : "r"(a[0]), "r"(a[1]), "r"(a[2]), "r"(a[3]), "r"(b[0]), "r"(b[1]));
}

// ================= 128x128 GEMM, row-major smem + scalar gather =================
// Operands must be PRE-ROUNDED to tf32 by their producers.
__device__ __forceinline__ void g_load2(const float* __restrict__ P, int ldp,
                                        int maxR, int K, int rBase, int k0,
                                        int tid, float4* out)
{
    int r0 = tid >> 2;
    int gk = k0 + (tid & 3) * 4;
    #pragma unroll
    for (int i = 0; i < 2; i++) {
        int gr = rBase + r0 + i * 64;
        float4 v = {0.f, 0.f, 0.f, 0.f};
        if (gr < maxR) {
            const float* p = P + (long long)gr * ldp + gk;
            if (gk + 3 < K) v = *(const float4*)p;
            else {
                if (gk     < K) v.x = p[0];
                if (gk + 1 < K) v.y = p[1];
                if (gk + 2 < K) v.z = p[2];
            }
        }
        out[i] = v;
    }
}

template<bool ACCUM>
__global__ __launch_bounds__(256, 2) void mma_gemm_kernel(
    const float* __restrict__ A, const float* __restrict__ B,
    const float* __restrict__ bias, float* __restrict__ C,
    int M, int N, int K, int lda, int ldb, int ldc, float alpha)
{
    __shared__ __align__(16) float smA[2][128 * RS_];
    __shared__ __align__(16) float smB[2][128 * RS_];

    int tid = threadIdx.x, lane = tid & 31, wid = tid >> 5;
    int warp_m = wid >> 2, warp_n = wid & 3;

    int rowBase = blockIdx.y * 128;
    int colBase = blockIdx.x * 128;
    int T = (K + 15) >> 4;

    float acc[4][4][4] = {};
    float4 pa[2], pb[2];
    int prow = tid >> 2, pk = (tid & 3) * 4;

    g_load2(A, lda, M, K, rowBase, 0, tid, pa);
    g_load2(B, ldb, N, K, colBase, 0, tid, pb);
    *(float4*)&smA[0][prow * RS_ + pk]        = pa[0];
    *(float4*)&smA[0][(prow + 64) * RS_ + pk] = pa[1];
    *(float4*)&smB[0][prow * RS_ + pk]        = pb[0];
    *(float4*)&smB[0][(prow + 64) * RS_ + pk] = pb[1];

    int qa = lane >> 2, ca = lane & 3;

    for (int t = 0; t < T; t++) {
        __syncthreads();
        if (t + 1 < T) {
            g_load2(A, lda, M, K, rowBase, (t + 1) << 4, tid, pa);
            g_load2(B, ldb, N, K, colBase, (t + 1) << 4, tid, pb);
        }
        const float* As = smA[t & 1];
        const float* Bs = smB[t & 1];
        #pragma unroll
        for (int kc = 0; kc < 2; kc++) {
            float af[4][4]; float bf[4][2];
            #pragma unroll
            for (int mt = 0; mt < 4; mt++) {
                const float* p = &As[(warp_m * 64 + mt * 16 + qa) * RS_ + kc * 8 + ca];
                af[mt][0] = p[0];
                af[mt][1] = p[8 * RS_];
                af[mt][2] = p[4];
                af[mt][3] = p[8 * RS_ + 4];
            }
            #pragma unroll
            for (int nt = 0; nt < 4; nt++) {
                const float* p = &Bs[(warp_n * 32 + nt * 8 + qa) * RS_ + kc * 8 + ca];
                bf[nt][0] = p[0];
                bf[nt][1] = p[4];
            }
            #pragma unroll
            for (int mt = 0; mt < 4; mt++)
                #pragma unroll
                for (int nt = 0; nt < 4; nt++)
                    mma8(acc[mt][nt], (const uint32_t*)af[mt], (const uint32_t*)bf[nt]);
        }
        if (t + 1 < T) {
            __syncthreads();
            float* Aw = smA[(t + 1) & 1];
            float* Bw = smB[(t + 1) & 1];
            *(float4*)&Aw[prow * RS_ + pk]        = pa[0];
            *(float4*)&Aw[(prow + 64) * RS_ + pk] = pa[1];
            *(float4*)&Bw[prow * RS_ + pk]        = pb[0];
            *(float4*)&Bw[(prow + 64) * RS_ + pk] = pb[1];
        }
    }

    int rw = rowBase + warp_m * 64;
    int cw = colBase + warp_n * 32;
    #pragma unroll
    for (int mt = 0; mt < 4; mt++) {
        #pragma unroll
        for (int nt = 0; nt < 4; nt++) {
            int r0 = rw + mt * 16 + (lane >> 2);
            int gc = cw + nt * 8 + (lane & 3) * 2;
            const float* cf = acc[mt][nt];
            #pragma unroll
            for (int half = 0; half < 2; half++) {
                int gr = r0 + half * 8;
                if (gr >= M) continue;
                float v0 = cf[half * 2]     * alpha;
                float v1 = cf[half * 2 + 1] * alpha;
                float* crow = C + (long long)gr * ldc;
                float2 b2 = *(const float2*)(bias + gc);
                v0 += b2.x; v1 += b2.y;
                if (ACCUM) {
                    float2 c2 = *(const float2*)(crow + gc);
                    v0 += c2.x; v1 += c2.y;
                }
                float2 o2 = {v0, v1};
                *(float2*)(crow + gc) = o2;
            }
        }
    }
}

// ================= fused flash attention (unchanged from R5 except o rounding) ======
#define ATTN_SMEM_BYTES (40960 * 4)

__global__ __launch_bounds__(256, 1) void attn_kernel(
    const float* __restrict__ q, const float* __restrict__ k,
    const float* __restrict__ v, float* __restrict__ o)
{
    extern __shared__ float sm[];
    float* Qs = sm;            // [mt 8][kc 8][32][4]
    float* Ks = sm + 8192;     // [nt 16][kc 8][32][2]
    float* Vs = sm + 16384;    // [ntv 8][kcv 16][32][2]
    float* Ps = sm + 24576;    // [warp 8][kcp 16][32][4]

    int tid = threadIdx.x, lane = tid & 31, wid = tid >> 5;
    int b = blockIdx.z, h = blockIdx.y, qb = blockIdx.x * 128;
    const long long base = (long long)b * S_ * D_ + h * DH_;

    #pragma unroll
    for (int i = 0; i < 8; i++) {
        int f4 = tid + i * 256;
        int row = f4 >> 4, c4 = f4 & 15;
        int gq = qb + row;
        float4 val = {0.f, 0.f, 0.f, 0.f};
        if (gq < S_) val = *(const float4*)(q + base + (long long)gq * D_ + c4 * 4);
        const float* vv = (const float*)&val;
        int mt = row >> 4, rr = row & 15;
        #pragma unroll
        for (int e = 0; e < 4; e++) {
            int col = c4 * 4 + e;
            int kc = col >> 3, cc = col & 7;
            Qs[((mt * 8 + kc) * 32 + (rr & 7) * 4 + (cc & 3)) * 4 + (rr >> 3) + 2 * (cc >> 2)]
                = f2tf32(vv[e] * 0.125f);
        }
    }

    float mrow[2] = {-1e30f, -1e30f};
    float lrow[2] = {0.f, 0.f};
    float oacc[8][4] = {};
    float* Pw = Ps + wid * 2048;

    for (int kt = 0; kt < 9; kt++) {
        int kb = kt * 128;
        __syncthreads();
        #pragma unroll
        for (int i = 0; i < 8; i++) {
            int f4 = tid + i * 256;
            int key = f4 >> 4, c4 = f4 & 15;
            int gk = kb + key;
            float4 kv = {0.f, 0.f, 0.f, 0.f}, vv = {0.f, 0.f, 0.f, 0.f};
            if (gk < S_) {
                kv = *(const float4*)(k + base + (long long)gk * D_ + c4 * 4);
                vv = *(const float4*)(v + base + (long long)gk * D_ + c4 * 4);
            }
            const float* kp = (const float*)&kv;
            const float* vp = (const float*)&vv;
            #pragma unroll
            for (int e = 0; e < 4; e++) {
                int dh = c4 * 4 + e;
                Ks[(((key >> 3) * 8 + (dh >> 3)) * 32 + (key & 7) * 4 + (dh & 3)) * 2
                   + ((dh >> 2) & 1)] = f2tf32(kp[e]);
                Vs[(((dh >> 3) * 16 + (key >> 3)) * 32 + (dh & 7) * 4 + (key & 3)) * 2
                   + ((key >> 2) & 1)] = f2tf32(vp[e]);
            }
        }
        __syncthreads();

        float acc[16][4] = {};
        #pragma unroll
        for (int kc = 0; kc < 8; kc++) {
            float4 af = *(const float4*)&Qs[((wid * 8 + kc) * 32 + lane) * 4];
            #pragma unroll
            for (int nt = 0; nt < 16; nt++) {
                float2 bf = *(const float2*)&Ks[((nt * 8 + kc) * 32 + lane) * 2];
                mma8(acc[nt], (const uint32_t*)&af, (const uint32_t*)&bf);
            }
        }

        int colb = (lane & 3) * 2;
        float tmax0 = -1e30f, tmax1 = -1e30f;
        #pragma unroll
        for (int nt = 0; nt < 16; nt++) {
            int c0 = kb + nt * 8 + colb;
            if (c0 < S_)     { tmax0 = fmaxf(tmax0, acc[nt][0]); tmax1 = fmaxf(tmax1, acc[nt][2]); }
            if (c0 + 1 < S_) { tmax0 = fmaxf(tmax0, acc[nt][1]); tmax1 = fmaxf(tmax1, acc[nt][3]); }
        }
        tmax0 = fmaxf(tmax0, __shfl_xor_sync(0xffffffffu, tmax0, 1));
        tmax0 = fmaxf(tmax0, __shfl_xor_sync(0xffffffffu, tmax0, 2));
        tmax1 = fmaxf(tmax1, __shfl_xor_sync(0xffffffffu, tmax1, 1));
        tmax1 = fmaxf(tmax1, __shfl_xor_sync(0xffffffffu, tmax1, 2));
        float mn0 = fmaxf(mrow[0], tmax0), mn1 = fmaxf(mrow[1], tmax1);
        float al0 = __expf(mrow[0] - mn0),  al1 = __expf(mrow[1] - mn1);
        float sum0 = 0.f, sum1 = 0.f;
        #pragma unroll
        for (int nt = 0; nt < 16; nt++) {
            int c0 = kb + nt * 8 + colb;
            float p0 = (c0     < S_) ? __expf(acc[nt][0] - mn0) : 0.f;
            float p1 = (c0 + 1 < S_) ? __expf(acc[nt][1] - mn0) : 0.f;
            float p2 = (c0     < S_) ? __expf(acc[nt][2] - mn1) : 0.f;
            float p3 = (c0 + 1 < S_) ? __expf(acc[nt][3] - mn1) : 0.f;
            acc[nt][0] = p0; acc[nt][1] = p1; acc[nt][2] = p2; acc[nt][3] = p3;
            sum0 += p0 + p1; sum1 += p2 + p3;
        }
        sum0 += __shfl_xor_sync(0xffffffffu, sum0, 1);
        sum0 += __shfl_xor_sync(0xffffffffu, sum0, 2);
        sum1 += __shfl_xor_sync(0xffffffffu, sum1, 1);
        sum1 += __shfl_xor_sync(0xffffffffu, sum1, 2);
        lrow[0] = lrow[0] * al0 + sum0;
        lrow[1] = lrow[1] * al1 + sum1;
        mrow[0] = mn0; mrow[1] = mn1;
        #pragma unroll
        for (int nt = 0; nt < 8; nt++) {
            oacc[nt][0] *= al0; oacc[nt][1] *= al0;
            oacc[nt][2] *= al1; oacc[nt][3] *= al1;
        }

        int rrA = lane >> 2;
        #pragma unroll
        for (int nt = 0; nt < 16; nt++) {
            #pragma unroll
            for (int e = 0; e < 2; e++) {
                int col = nt * 8 + colb + e;
                int kcp = col >> 3, cc = col & 7;
                int ln = rrA * 4 + (cc & 3);
                int rh = 2 * (cc >> 2);
                Pw[(kcp * 32 + ln) * 4 + rh]     = f2tf32(acc[nt][e]);
                Pw[(kcp * 32 + ln) * 4 + rh + 1] = f2tf32(acc[nt][e + 2]);
            }
        }
        __syncwarp();

        #pragma unroll
        for (int kcv = 0; kcv < 16; kcv++) {
            float4 paf = *(const float4*)&Pw[(kcv * 32 + lane) * 4];
            #pragma unroll
            for (int ntv = 0; ntv < 8; ntv++) {
                float2 bf = *(const float2*)&Vs[((ntv * 16 + kcv) * 32 + lane) * 2];
                mma8(oacc[ntv], (const uint32_t*)&paf, (const uint32_t*)&bf);
            }
        }
        __syncwarp();
    }

    int row = wid * 16 + (lane >> 2);
    #pragma unroll
    for (int half = 0; half < 2; half++) {
        int gq = qb + row + half * 8;
        if (gq >= S_) continue;
        float invl = 1.f / lrow[half];
        float* orow = o + base + (long long)gq * D_;
        #pragma unroll
        for (int ntv = 0; ntv < 8; ntv++) {
            int col = ntv * 8 + (lane & 3) * 2;
            float2 val = { f2tf32(oacc[ntv][half * 2] * invl),
                           f2tf32(oacc[ntv][half * 2 + 1] * invl) };
            *(float2*)(orow + col) = val;
        }
    }
}

// ================= transposes (now tf32-round the output: weights feed GEMM B) ======
__global__ void transpose_kernel(const float* __restrict__ src, float* __restrict__ dst,
                                 int R, int C, long long sS, long long sD)
{
    __shared__ float t[32][33];
    const float* s = src + (long long)blockIdx.z * sS;
    float* d = dst + (long long)blockIdx.z * sD;
    int c0 = blockIdx.x * 32, r0 = blockIdx.y * 32;
    #pragma unroll
    for (int i = 0; i < 4; i++) {
        int r = r0 + threadIdx.y + i * 8, c = c0 + threadIdx.x;
        if (r < R && c < C) t[threadIdx.y + i * 8][threadIdx.x] = s[(long long)r * C + c];
    }
    __syncthreads();
    #pragma unroll
    for (int i = 0; i < 4; i++) {
        int r = c0 + threadIdx.y + i * 8, c = r0 + threadIdx.x;
        if (r < C && c < R) d[(long long)r * R + c] = f2tf32(t[threadIdx.x][threadIdx.y + i * 8]);
    }
}

// ================= layernorm =================
template<bool ROUND>
__device__ __forceinline__ void ln_row_1024(const float* __restrict__ x,
                                            float* __restrict__ y,
                                            const float* __restrict__ gw,
                                            const float* __restrict__ bw)
{
    __shared__ float sh1[32], sh2[32];
    float v[4];
    float s = 0.f, ss = 0.f;
    #pragma unroll
    for (int i = 0; i < 4; i++) {
        v[i] = x[threadIdx.x + i * 256];
        s += v[i]; ss += v[i] * v[i];
    }
    #pragma unroll
    for (int o = 16; o > 0; o >>= 1) {
        s  += __shfl_down_sync(0xffffffffu, s,  o);
        ss += __shfl_down_sync(0xffffffffu, ss, o);
    }
    int lane = threadIdx.x & 31, w = threadIdx.x >> 5;
    if (lane == 0) { sh1[w] = s; sh2[w] = ss; }
    __syncthreads();
    if (w == 0) {
        s  = lane < 8 ? sh1[lane] : 0.f;
        ss = lane < 8 ? sh2[lane] : 0.f;
        #pragma unroll
        for (int o = 4; o > 0; o >>= 1) {
            s  += __shfl_down_sync(0xffffffffu, s,  o);
            ss += __shfl_down_sync(0xffffffffu, ss, o);
        }
        if (lane == 0) { sh1[0] = s; sh2[0] = ss; }
    }
    __syncthreads();
    float mu  = sh1[0] * (1.f / D_);
    float var = sh2[0] * (1.f / D_) - mu * mu;
    float inv = rsqrtf(var + 1e-5f);
    #pragma unroll
    for (int i = 0; i < 4; i++) {
        int c = threadIdx.x + i * 256;
        float val = (v[i] - mu) * inv * gw[c] + bw[c];
        y[c] = ROUND ? f2tf32(val) : val;
    }
}

template<bool ROUND>
__global__ void layernorm_kernel(const float* __restrict__ in, float* __restrict__ out,
                                 const float* __restrict__ gw, const float* __restrict__ bw)
{
    long long row = blockIdx.x;
    ln_row_1024<ROUND>(in + row * D_, out + row * D_, gw, bw);
}

__global__ void patch_ln_kernel(const float* __restrict__ pe, float* __restrict__ h,
                                const float* __restrict__ gw, const float* __restrict__ bw)
{
    int row = blockIdx.x;
    int b = row >> 10, p = row & 1023;
    ln_row_1024<false>(pe + (long long)row * D_, h + ((long long)b * S_ + 1 + p) * D_, gw, bw);
}

// ================= misc elementwise =================
__global__ void patchify_kernel(const float* __restrict__ x, float* __restrict__ p)
{
    long long t = (long long)blockIdx.x * blockDim.x + threadIdx.x;
    const long long total = (long long)B_ * NP_ * NM_ * PS_;
    if (t >= total) return;
    int c   = (int)(t & 2047);
    long long bp = t >> 11;
    int pidx = (int)(bp & (NP_ - 1));
    int b    = (int)(bp >> 10);
    int m  = c >> 4;
    int tt = c & 15;
    p[t] = f2tf32(x[((long long)b * NM_ + m) * (PS_ * NP_) + (long long)pidx * PS_ + tt]);
}

__global__ void cls_kernel(float* __restrict__ h, const float* __restrict__ cls)
{
    int t = blockIdx.x * blockDim.x + threadIdx.x;
    if (t >= B_ * D_) return;
    int b = t >> 10, i = t & 1023;
    h[(long long)b * S_ * D_ + i] = cls[i];
}

__global__ void rope_table_kernel(float* __restrict__ ct, float* __restrict__ st)
{
    int idx = blockIdx.x * blockDim.x + threadIdx.x;
    if (idx >= S_ * (DH_ / 2)) return;
    int i = idx & 31, s = idx >> 5;
    double invf = pow(10000.0, -(double)(2 * i) / (double)DH_);
    double ang  = (double)s * invf;
    ct[idx] = (float)cos(ang);
    st[idx] = (float)sin(ang);
}

__global__ void rope_kernel(float* __restrict__ q, float* __restrict__ k,
                            const float* __restrict__ ct, const float* __restrict__ st)
{
    long long t = (long long)blockIdx.x * blockDim.x + threadIdx.x;
    const long long total = (long long)B_ * S_ * H_ * (DH_ / 2);
    if (t >= total) return;
    int i = (int)(t & 31);
    long long r = t >> 5;
    int h = (int)(r & (H_ - 1));
    long long bs = r >> 4;
    int s = (int)(bs % S_);
    float c  = ct[s * 32 + i];
    float sn = st[s * 32 + i];
    long long base = bs * D_ + (long long)h * DH_;
    float q0 = q[base + i], q1 = q[base + i + 32];
    q[base + i]      = q0 * c - q1 * sn;
    q[base + i + 32] = q1 * c + q0 * sn;
    float k0 = k[base + i], k1 = k[base + i + 32];
    k[base + i]      = k0 * c - k1 * sn;
    k[base + i + 32] = k1 * c + k0 * sn;
}

__global__ void swiglu_kernel(float* __restrict__ a1, const float* __restrict__ a3)
{
    long long t = (long long)blockIdx.x * blockDim.x + threadIdx.x;
    const long long total = (long long)B_ * S_ * FF_;
    if (t >= total) return;
    float x = a1[t];
    float sig = 1.f / (1.f + expf(-x));
    a1[t] = f2tf32(x * sig * a3[t]);
}

// ================= host side =================
static inline void run_gemm128(const float* A, const float* B, const float* bias, float* C,
                               int M, int N, int K, int lda, int ldb, int ldc,
                               float alpha, bool accum)
{
    dim3 grid((N + 127) / 128, (M + 127) / 128), block(256);
    if (accum)
        mma_gemm_kernel<true><<<grid, block>>>(A, B, bias, C, M, N, K, lda, ldb, ldc, alpha);
    else
        mma_gemm_kernel<false><<<grid, block>>>(A, B, bias, C, M, N, K, lda, ldb, ldc, alpha);
}

extern "C" void kernel_launch(void* const* d_in, const int* in_sizes, int n_in,
                              void* d_out, int out_size)
{
    (void)in_sizes; (void)n_in; (void)out_size;
    const float* x        = (const float*)d_in[0];
    const float* patch_w  = (const float*)d_in[1];
    const float* patch_b  = (const float*)d_in[2];
    const float* pln_g    = (const float*)d_in[3];
    const float* pln_b    = (const float*)d_in[4];
    const float* cls_tok  = (const float*)d_in[5];
    const float* ln1_g    = (const float*)d_in[6];
    const float* ln1_b    = (const float*)d_in[7];
    const float* wq       = (const float*)d_in[8];
    const float* bq       = (const float*)d_in[9];
    const float* wk       = (const float*)d_in[10];
    const float* bk       = (const float*)d_in[11];
    const float* wv       = (const float*)d_in[12];
    const float* bv       = (const float*)d_in[13];
    const float* wo       = (const float*)d_in[14];
    const float* bo       = (const float*)d_in[15];
    const float* ln2_g    = (const float*)d_in[16];
    const float* ln2_b    = (const float*)d_in[17];
    const float* w1       = (const float*)d_in[18];
    const float* b1       = (const float*)d_in[19];
    const float* w2       = (const float*)d_in[20];
    const float* b2       = (const float*)d_in[21];
    const float* w3       = (const float*)d_in[22];
    const float* b3       = (const float*)d_in[23];
    const float* lnf_g    = (const float*)d_in[24];
    const float* lnf_b    = (const float*)d_in[25];
    float* out = (float*)d_out;

    float *patches, *pe, *h, *y, *q, *k, *v, *o, *a1, *a3, *ct, *st;
    float *pwT, *wqT, *wkT, *wvT, *woT, *w1T, *w3T, *w2T;
    cudaGetSymbolAddress((void**)&patches, g_patches);
    cudaGetSymbolAddress((void**)&pe, g_pe);
    cudaGetSymbolAddress((void**)&h,  g_h);
    cudaGetSymbolAddress((void**)&y,  g_y);
    cudaGetSymbolAddress((void**)&q,  g_q);
    cudaGetSymbolAddress((void**)&k,  g_k);
    cudaGetSymbolAddress((void**)&v,  g_v);
    cudaGetSymbolAddress((void**)&o,  g_o);
    cudaGetSymbolAddress((void**)&a1, g_a1);
    cudaGetSymbolAddress((void**)&a3, g_a3);
    cudaGetSymbolAddress((void**)&ct, g_cos);
    cudaGetSymbolAddress((void**)&st, g_sin);
    cudaGetSymbolAddress((void**)&pwT, g_pwT);
    cudaGetSymbolAddress((void**)&wqT, g_wqT);
    cudaGetSymbolAddress((void**)&wkT, g_wkT);
    cudaGetSymbolAddress((void**)&wvT, g_wvT);
    cudaGetSymbolAddress((void**)&woT, g_woT);
    cudaGetSymbolAddress((void**)&w1T, g_w1T);
    cudaGetSymbolAddress((void**)&w3T, g_w3T);
    cudaGetSymbolAddress((void**)&w2T, g_w2T);

    cudaFuncSetAttribute(attn_kernel, cudaFuncAttributeMaxDynamicSharedMemorySize,
                         ATTN_SMEM_BYTES);

    const int MR = B_ * S_;
    dim3 tb(32, 8);

    // weight transposes to [N,K] K-major, tf32-rounded
    transpose_kernel<<<dim3(32, 64, 1),  tb>>>(patch_w, pwT, NM_ * PS_, D_, 0, 0);
    transpose_kernel<<<dim3(32, 32, L_), tb>>>(wq, wqT, D_, D_, (long long)D_ * D_, (long long)D_ * D_);
    transpose_kernel<<<dim3(32, 32, L_), tb>>>(wk, wkT, D_, D_, (long long)D_ * D_, (long long)D_ * D_);
    transpose_kernel<<<dim3(32, 32, L_), tb>>>(wv, wvT, D_, D_, (long long)D_ * D_, (long long)D_ * D_);
    transpose_kernel<<<dim3(32, 32, L_), tb>>>(wo, woT, D_, D_, (long long)D_ * D_, (long long)D_ * D_);
    transpose_kernel<<<dim3(128, 32, L_), tb>>>(w1, w1T, D_, FF_, (long long)D_ * FF_, (long long)D_ * FF_);
    transpose_kernel<<<dim3(128, 32, L_), tb>>>(w3, w3T, D_, FF_, (long long)D_ * FF_, (long long)D_ * FF_);
    transpose_kernel<<<dim3(32, 128, L_), tb>>>(w2, w2T, FF_, D_, (long long)D_ * FF_, (long long)D_ * FF_);

    {
        long long n = (long long)B_ * NP_ * NM_ * PS_;
        patchify_kernel<<<(int)((n + 255) / 256), 256>>>(x, patches);
    }
    rope_table_kernel<<<(S_ * 32 + 255) / 256, 256>>>(ct, st);

    run_gemm128(patches, pwT, patch_b, pe, B_ * NP_, D_, NM_ * PS_,
                NM_ * PS_, NM_ * PS_, D_, 1.f, false);
    patch_ln_kernel<<<B_ * NP_, 256>>>(pe, h, pln_g, pln_b);
    cls_kernel<<<(B_ * D_ + 255) / 256, 256>>>(h, cls_tok);

    for (int l = 0; l < L_; l++) {
        const float* WqT = wqT + (size_t)l * D_ * D_;
        const float* WkT = wkT + (size_t)l * D_ * D_;
        const float* WvT = wvT + (size_t)l * D_ * D_;
        const float* WoT = woT + (size_t)l * D_ * D_;
        const float* W1T = w1T + (size_t)l * D_ * FF_;
        const float* W3T = w3T + (size_t)l * D_ * FF_;
        const float* W2T = w2T + (size_t)l * D_ * FF_;

        layernorm_kernel<true><<<MR, 256>>>(h, y, ln1_g + (size_t)l * D_, ln1_b + (size_t)l * D_);

        run_gemm128(y, WqT, bq + (size_t)l * D_, q, MR, D_, D_, D_, D_, D_, 1.f, false);
        run_gemm128(y, WkT, bk + (size_t)l * D_, k, MR, D_, D_, D_, D_, D_, 1.f, false);
        run_gemm128(y, WvT, bv + (size_t)l * D_, v, MR, D_, D_, D_, D_, D_, 1.f, false);

        {
            long long n = (long long)B_ * S_ * H_ * (DH_ / 2);
            rope_kernel<<<(int)((n + 255) / 256), 256>>>(q, k, ct, st);
        }

        attn_kernel<<<dim3(9, H_, B_), 256, ATTN_SMEM_BYTES>>>(q, k, v, o);

        run_gemm128(o, WoT, bo + (size_t)l * D_, h, MR, D_, D_, D_, D_, D_, 1.f, true);

        layernorm_kernel<true><<<MR, 256>>>(h, y, ln2_g + (size_t)l * D_, ln2_b + (size_t)l * D_);

        run_gemm128(y, W1T, b1 + (size_t)l * FF_, a1, MR, FF_, D_, D_, D_, FF_, 1.f, false);
        run_gemm128(y, W3T, b3 + (size_t)l * FF_, a3, MR, FF_, D_, D_, D_, FF_, 1.f, false);

        {
            long long n = (long long)B_ * S_ * FF_;
            swiglu_kernel<<<(int)((n + 255) / 256), 256>>>(a1, a3);
        }

        run_gemm128(a1, W2T, b2 + (size_t)l * D_, h, MR, D_, FF_, FF_, FF_, D_, 1.f, true);
    }

    layernorm_kernel<false><<<MR, 256>>>(h, out, lnf_g, lnf_b);
}